// round 2
// baseline (speedup 1.0000x reference)
#include <cuda_runtime.h>

#define Dd 96
#define Hh 160
#define Ww 160
#define DHW (Dd*Hh*Ww)

// scratch: two composed-flow fields, interleaved float4 (z,y,x,pad)
__device__ float4 g_I0[DHW];
__device__ float4 g_I1[DHW];

// coord(v,s) = v*s/(s-1) - 0.5  (normalize_grid + grid_sample denorm, fused)
#define SZC ((float)Dd / (float)(Dd - 1))
#define SYC ((float)Hh / (float)(Hh - 1))
#define SXC ((float)Ww / (float)(Ww - 1))

// Build 8 clamped corner offsets + zero-padded trilinear weights.
__device__ __forceinline__ void make_corners(float cz, float cy, float cx,
                                             int off[8], float w[8]) {
    float z0f = floorf(cz), y0f = floorf(cy), x0f = floorf(cx);
    float tz = cz - z0f, ty = cy - y0f, tx = cx - x0f;
    int z0 = (int)z0f, y0 = (int)y0f, x0 = (int)x0f;
    int z1 = z0 + 1,  y1 = y0 + 1,  x1 = x0 + 1;

    float wz0 = (z0 >= 0 && z0 < Dd) ? (1.f - tz) : 0.f;
    float wz1 = (z1 >= 0 && z1 < Dd) ? tz         : 0.f;
    float wy0 = (y0 >= 0 && y0 < Hh) ? (1.f - ty) : 0.f;
    float wy1 = (y1 >= 0 && y1 < Hh) ? ty         : 0.f;
    float wx0 = (x0 >= 0 && x0 < Ww) ? (1.f - tx) : 0.f;
    float wx1 = (x1 >= 0 && x1 < Ww) ? tx         : 0.f;

    int z0c = min(max(z0, 0), Dd - 1), z1c = min(max(z1, 0), Dd - 1);
    int y0c = min(max(y0, 0), Hh - 1), y1c = min(max(y1, 0), Hh - 1);
    int x0c = min(max(x0, 0), Ww - 1), x1c = min(max(x1, 0), Ww - 1);

    int b00 = (z0c * Hh + y0c) * Ww;
    int b01 = (z0c * Hh + y1c) * Ww;
    int b10 = (z1c * Hh + y0c) * Ww;
    int b11 = (z1c * Hh + y1c) * Ww;

    off[0] = b00 + x0c;  w[0] = wz0 * wy0 * wx0;
    off[1] = b00 + x1c;  w[1] = wz0 * wy0 * wx1;
    off[2] = b01 + x0c;  w[2] = wz0 * wy1 * wx0;
    off[3] = b01 + x1c;  w[3] = wz0 * wy1 * wx1;
    off[4] = b10 + x0c;  w[4] = wz1 * wy0 * wx0;
    off[5] = b10 + x1c;  w[5] = wz1 * wy0 * wx1;
    off[6] = b11 + x0c;  w[6] = wz1 * wy1 * wx0;
    off[7] = b11 + x1c;  w[7] = wz1 * wy1 * wx1;
}

// Gather interleaved float4 field trilinearly -> (vz, vy, vx)
__device__ __forceinline__ void gather4(const float4* __restrict__ f,
                                        const int off[8], const float w[8],
                                        float& vz, float& vy, float& vx) {
    vz = 0.f; vy = 0.f; vx = 0.f;
    #pragma unroll
    for (int k = 0; k < 8; k++) {
        float4 v = __ldg(f + off[k]);
        vz = fmaf(w[k], v.x, vz);
        vy = fmaf(w[k], v.y, vy);
        vx = fmaf(w[k], v.z, vx);
    }
}

// Pack planar [3,DHW] -> interleaved float4
__global__ void __launch_bounds__(256)
pack_kernel(const float* __restrict__ pl, float4* __restrict__ out) {
    int idx = blockIdx.x * blockDim.x + threadIdx.x;
    if (idx >= DHW) return;
    out[idx] = make_float4(pl[idx], pl[idx + DHW], pl[idx + 2 * DHW], 0.f);
}

// One compose step: out = trilerp(comp, base + dvf*rf) + dvf  (float4 in/out)
__global__ void __launch_bounds__(256)
warp_step(const float4* __restrict__ comp, const float* __restrict__ dvf,
          float4* __restrict__ out, const float* __restrict__ rfp) {
    int idx = blockIdx.x * blockDim.x + threadIdx.x;
    if (idx >= DHW) return;
    float rf = __ldg(rfp);

    int x = idx % Ww;
    int y = (idx / Ww) % Hh;
    int z = idx / (Ww * Hh);

    float fz = dvf[idx];
    float fy = dvf[idx + DHW];
    float fx = dvf[idx + 2 * DHW];

    float cz = fmaf(fz * rf, SZC, (float)z * SZC - 0.5f);
    float cy = fmaf(fy * rf, SYC, (float)y * SYC - 0.5f);
    float cx = fmaf(fx * rf, SXC, (float)x * SXC - 0.5f);

    int off[8]; float w[8];
    make_corners(cz, cy, cx, off, w);

    float vz, vy, vx;
    gather4(comp, off, w, vz, vy, vx);

    out[idx] = make_float4(vz + fz, vy + fy, vx + fx, 0.f);
}

// Final fused step:
//  composed3 = trilerp(comp, base+ff*rf) + ff -> out_flow (planar)
//  deform    = trilerp(src,  base+composed3*rf)
__global__ void __launch_bounds__(256)
warp_final(const float4* __restrict__ comp, const float* __restrict__ ff,
           const float* __restrict__ src, float* __restrict__ out_deform,
           float* __restrict__ out_flow, const float* __restrict__ rfp) {
    int idx = blockIdx.x * blockDim.x + threadIdx.x;
    if (idx >= DHW) return;
    float rf = __ldg(rfp);

    int x = idx % Ww;
    int y = (idx / Ww) % Hh;
    int z = idx / (Ww * Hh);

    float fz = ff[idx];
    float fy = ff[idx + DHW];
    float fx = ff[idx + 2 * DHW];

    float cz = fmaf(fz * rf, SZC, (float)z * SZC - 0.5f);
    float cy = fmaf(fy * rf, SYC, (float)y * SYC - 0.5f);
    float cx = fmaf(fx * rf, SXC, (float)x * SXC - 0.5f);

    int off[8]; float w[8];
    make_corners(cz, cy, cx, off, w);

    float vz, vy, vx;
    gather4(comp, off, w, vz, vy, vx);

    float coz = vz + fz, coy = vy + fy, cox = vx + fx;
    out_flow[idx]            = coz;
    out_flow[idx + DHW]      = coy;
    out_flow[idx + 2 * DHW]  = cox;

    // second sample: src at base + composed3*rf
    float cz2 = fmaf(coz * rf, SZC, (float)z * SZC - 0.5f);
    float cy2 = fmaf(coy * rf, SYC, (float)y * SYC - 0.5f);
    float cx2 = fmaf(cox * rf, SXC, (float)x * SXC - 0.5f);

    int off2[8]; float w2[8];
    make_corners(cz2, cy2, cx2, off2, w2);

    float s = 0.f;
    #pragma unroll
    for (int k = 0; k < 8; k++) s = fmaf(w2[k], __ldg(src + off2[k]), s);
    out_deform[idx] = s;
}

extern "C" void kernel_launch(void* const* d_in, const int* in_sizes, int n_in,
                              void* d_out, int out_size) {
    const float* src        = (const float*)d_in[0];   // [1,1,D,H,W]
    const float* flow_list  = (const float*)d_in[1];   // [3,1,3,D,H,W]
    const float* final_flow = (const float*)d_in[2];   // [1,3,D,H,W]
    const float* rfp        = (const float*)d_in[3];   // scalar

    float* out_deform = (float*)d_out;          // [D*H*W]
    float* out_flow   = (float*)d_out + DHW;    // [3*D*H*W]

    float4 *I0, *I1;
    cudaGetSymbolAddress((void**)&I0, g_I0);
    cudaGetSymbolAddress((void**)&I1, g_I1);

    const int threads = 256;
    const int blocks = (DHW + threads - 1) / threads;

    // pack flow_list[0] planar -> interleaved
    pack_kernel<<<blocks, threads>>>(flow_list, I0);
    // iter 1: comp = I0, dvf = flow_list[1] -> I1
    warp_step<<<blocks, threads>>>(I0, flow_list + 3 * DHW, I1, rfp);
    // iter 2: comp = I1, dvf = flow_list[2] -> I0 (reuse)
    warp_step<<<blocks, threads>>>(I1, flow_list + 6 * DHW, I0, rfp);
    // iter 3 + final src sample fused
    warp_final<<<blocks, threads>>>(I0, final_flow, src, out_deform, out_flow, rfp);
}

// round 3
// speedup vs baseline: 1.1358x; 1.1358x over previous
#include <cuda_runtime.h>

#define Dd 96
#define Hh 160
#define Ww 160
#define DHW (Dd*Hh*Ww)

// scratch: packed composed-flow fields: float2 (z,y) + float plane (x)
__device__ float2 g_A2[DHW];
__device__ float  g_A1[DHW];
__device__ float2 g_B2[DHW];
__device__ float  g_B1[DHW];

// coord(v,s) = v*s/(s-1) - 0.5  (normalize_grid + grid_sample denorm, fused)
#define SZC ((float)Dd / (float)(Dd - 1))
#define SYC ((float)Hh / (float)(Hh - 1))
#define SXC ((float)Ww / (float)(Ww - 1))

// Build 8 clamped corner offsets + zero-padded trilinear weights.
__device__ __forceinline__ void make_corners(float cz, float cy, float cx,
                                             int off[8], float w[8]) {
    float z0f = floorf(cz), y0f = floorf(cy), x0f = floorf(cx);
    float tz = cz - z0f, ty = cy - y0f, tx = cx - x0f;
    int z0 = (int)z0f, y0 = (int)y0f, x0 = (int)x0f;
    int z1 = z0 + 1,  y1 = y0 + 1,  x1 = x0 + 1;

    float wz0 = (z0 >= 0 && z0 < Dd) ? (1.f - tz) : 0.f;
    float wz1 = (z1 >= 0 && z1 < Dd) ? tz         : 0.f;
    float wy0 = (y0 >= 0 && y0 < Hh) ? (1.f - ty) : 0.f;
    float wy1 = (y1 >= 0 && y1 < Hh) ? ty         : 0.f;
    float wx0 = (x0 >= 0 && x0 < Ww) ? (1.f - tx) : 0.f;
    float wx1 = (x1 >= 0 && x1 < Ww) ? tx         : 0.f;

    int z0c = min(max(z0, 0), Dd - 1), z1c = min(max(z1, 0), Dd - 1);
    int y0c = min(max(y0, 0), Hh - 1), y1c = min(max(y1, 0), Hh - 1);
    int x0c = min(max(x0, 0), Ww - 1), x1c = min(max(x1, 0), Ww - 1);

    int b00 = (z0c * Hh + y0c) * Ww;
    int b01 = (z0c * Hh + y1c) * Ww;
    int b10 = (z1c * Hh + y0c) * Ww;
    int b11 = (z1c * Hh + y1c) * Ww;

    off[0] = b00 + x0c;  w[0] = wz0 * wy0 * wx0;
    off[1] = b00 + x1c;  w[1] = wz0 * wy0 * wx1;
    off[2] = b01 + x0c;  w[2] = wz0 * wy1 * wx0;
    off[3] = b01 + x1c;  w[3] = wz0 * wy1 * wx1;
    off[4] = b10 + x0c;  w[4] = wz1 * wy0 * wx0;
    off[5] = b10 + x1c;  w[5] = wz1 * wy0 * wx1;
    off[6] = b11 + x0c;  w[6] = wz1 * wy1 * wx0;
    off[7] = b11 + x1c;  w[7] = wz1 * wy1 * wx1;
}

// idx/coords from 3D tiled launch: block (32,8,1), grid (W/32, H/8, D)
__device__ __forceinline__ void tile_coords(int& x, int& y, int& z, int& idx) {
    x = blockIdx.x * 32 + threadIdx.x;
    y = blockIdx.y * 8 + threadIdx.y;
    z = blockIdx.z;
    idx = (z * Hh + y) * Ww + x;
}

__device__ __forceinline__ void coord_from_flow(int x, int y, int z, float rf,
                                                float fz, float fy, float fx,
                                                float& cz, float& cy, float& cx) {
    cz = fmaf(fz * rf, SZC, (float)z * SZC - 0.5f);
    cy = fmaf(fy * rf, SYC, (float)y * SYC - 0.5f);
    cx = fmaf(fx * rf, SXC, (float)x * SXC - 0.5f);
}

// Gather packed field (float2 zy + float x plane)
__device__ __forceinline__ void gather_packed(const float2* __restrict__ p2,
                                              const float* __restrict__ p1,
                                              const int off[8], const float w[8],
                                              float& vz, float& vy, float& vx) {
    vz = 0.f; vy = 0.f; vx = 0.f;
    #pragma unroll
    for (int k = 0; k < 8; k++) {
        float2 v = __ldg(p2 + off[k]);
        vz = fmaf(w[k], v.x, vz);
        vy = fmaf(w[k], v.y, vy);
        vx = fmaf(w[k], __ldg(p1 + off[k]), vx);
    }
}

// Step 1: comp is PLANAR (flow_list[0]); dvf planar; output packed.
__global__ void __launch_bounds__(256)
step_planar(const float* __restrict__ comp, const float* __restrict__ dvf,
            float2* __restrict__ o2, float* __restrict__ o1,
            const float* __restrict__ rfp) {
    int x, y, z, idx; tile_coords(x, y, z, idx);
    float rf = __ldg(rfp);

    float fz = dvf[idx], fy = dvf[idx + DHW], fx = dvf[idx + 2 * DHW];
    float cz, cy, cx; coord_from_flow(x, y, z, rf, fz, fy, fx, cz, cy, cx);

    int off[8]; float w[8];
    make_corners(cz, cy, cx, off, w);

    float vz = 0.f, vy = 0.f, vx = 0.f;
    const float* cpz = comp;
    const float* cpy = comp + DHW;
    const float* cpx = comp + 2 * DHW;
    #pragma unroll
    for (int k = 0; k < 8; k++) {
        vz = fmaf(w[k], __ldg(cpz + off[k]), vz);
        vy = fmaf(w[k], __ldg(cpy + off[k]), vy);
        vx = fmaf(w[k], __ldg(cpx + off[k]), vx);
    }

    o2[idx] = make_float2(vz + fz, vy + fy);
    o1[idx] = vx + fx;
}

// Step 2: comp packed; dvf planar; output packed.
__global__ void __launch_bounds__(256)
step_packed(const float2* __restrict__ c2, const float* __restrict__ c1,
            const float* __restrict__ dvf,
            float2* __restrict__ o2, float* __restrict__ o1,
            const float* __restrict__ rfp) {
    int x, y, z, idx; tile_coords(x, y, z, idx);
    float rf = __ldg(rfp);

    float fz = dvf[idx], fy = dvf[idx + DHW], fx = dvf[idx + 2 * DHW];
    float cz, cy, cx; coord_from_flow(x, y, z, rf, fz, fy, fx, cz, cy, cx);

    int off[8]; float w[8];
    make_corners(cz, cy, cx, off, w);

    float vz, vy, vx;
    gather_packed(c2, c1, off, w, vz, vy, vx);

    o2[idx] = make_float2(vz + fz, vy + fy);
    o1[idx] = vx + fx;
}

// Final fused: composed3 = trilerp(comp, base+ff*rf) + ff -> out_flow planar
//              deform    = trilerp(src,  base+composed3*rf)
__global__ void __launch_bounds__(256)
warp_final(const float2* __restrict__ c2, const float* __restrict__ c1,
           const float* __restrict__ ff, const float* __restrict__ src,
           float* __restrict__ out_deform, float* __restrict__ out_flow,
           const float* __restrict__ rfp) {
    int x, y, z, idx; tile_coords(x, y, z, idx);
    float rf = __ldg(rfp);

    float fz = ff[idx], fy = ff[idx + DHW], fx = ff[idx + 2 * DHW];
    float cz, cy, cx; coord_from_flow(x, y, z, rf, fz, fy, fx, cz, cy, cx);

    int off[8]; float w[8];
    make_corners(cz, cy, cx, off, w);

    float vz, vy, vx;
    gather_packed(c2, c1, off, w, vz, vy, vx);

    float coz = vz + fz, coy = vy + fy, cox = vx + fx;
    out_flow[idx]           = coz;
    out_flow[idx + DHW]     = coy;
    out_flow[idx + 2 * DHW] = cox;

    float cz2, cy2, cx2; coord_from_flow(x, y, z, rf, coz, coy, cox, cz2, cy2, cx2);

    int off2[8]; float w2[8];
    make_corners(cz2, cy2, cx2, off2, w2);

    float s = 0.f;
    #pragma unroll
    for (int k = 0; k < 8; k++) s = fmaf(w2[k], __ldg(src + off2[k]), s);
    out_deform[idx] = s;
}

extern "C" void kernel_launch(void* const* d_in, const int* in_sizes, int n_in,
                              void* d_out, int out_size) {
    const float* src        = (const float*)d_in[0];   // [1,1,D,H,W]
    const float* flow_list  = (const float*)d_in[1];   // [3,1,3,D,H,W]
    const float* final_flow = (const float*)d_in[2];   // [1,3,D,H,W]
    const float* rfp        = (const float*)d_in[3];   // scalar

    float* out_deform = (float*)d_out;          // [D*H*W]
    float* out_flow   = (float*)d_out + DHW;    // [3*D*H*W]

    float2 *A2, *B2; float *A1, *B1;
    cudaGetSymbolAddress((void**)&A2, g_A2);
    cudaGetSymbolAddress((void**)&A1, g_A1);
    cudaGetSymbolAddress((void**)&B2, g_B2);
    cudaGetSymbolAddress((void**)&B1, g_B1);

    dim3 block(32, 8, 1);
    dim3 grid(Ww / 32, Hh / 8, Dd);

    // iter 1: comp = flow_list[0] (planar), dvf = flow_list[1] -> packed A
    step_planar<<<grid, block>>>(flow_list, flow_list + 3 * DHW, A2, A1, rfp);
    // iter 2: comp = A (packed), dvf = flow_list[2] -> packed B
    step_packed<<<grid, block>>>(A2, A1, flow_list + 6 * DHW, B2, B1, rfp);
    // iter 3 + final src sample fused
    warp_final<<<grid, block>>>(B2, B1, final_flow, src, out_deform, out_flow, rfp);
}